// round 11
// baseline (speedup 1.0000x reference)
#include <cuda_runtime.h>
#include <cuda_fp16.h>
#include <mma.h>
#include <cstdint>
#include <math.h>

using namespace nvcuda;

#define B_ 32
#define N_ 8192
#define D_ 1024
#define H_ 128
#define CPB 64          // CTAs per batch in gemm1 (8192/128)

// ---------------- scratch (no cudaMalloc allowed) ----------------
__device__ __align__(16) unsigned short g_w1t[H_ * D_];   // fp16 W1^T [h][d]
__device__ __align__(16) float g_e[B_ * N_];              // mask*exp(logit)
__device__ __align__(16) float g_erow[B_ * CPB];          // per-CTA e sums
__device__ __align__(16) float g_part[B_ * CPB * D_];     // unscaled pooled partials (8 MB)

// ---------------- helpers ----------------
__device__ __forceinline__ uint32_t smem_u32(const void* p) {
    uint32_t a;
    asm("{ .reg .u64 t; cvta.to.shared.u64 t, %1; cvt.u32.u64 %0, t; }" : "=r"(a) : "l"(p));
    return a;
}
__device__ __forceinline__ void cpasync16(uint32_t dst, const void* src) {
    asm volatile("cp.async.cg.shared.global [%0], [%1], 16;"
                 :: "r"(dst), "l"(src) : "memory");
}

// ---------------- kernel 0: W1^T -> fp16 ----------------
__global__ void prep_kernel(const float* __restrict__ w1) {
    int idx = blockIdx.x * 256 + threadIdx.x;   // 0..H*D-1
    int h = idx >> 10, d = idx & 1023;
    g_w1t[idx] = __half_as_ushort(__float2half_rn(w1[(size_t)d * H_ + h]));
}

// ---------------- kernel 1: GEMM1 + tanh + fc2 + exp*mask + weighted pool ----------------
static constexpr int ROWE = 72;                  // row stride in fp16 elements
static constexpr int ROWB = 144;                 // row stride bytes (128 data + 16 pad)
static constexpr int TILE = 128 * ROWB;          // 18432 bytes per 128x64 tile
static constexpr int OFF_B1   = 0;               // 512 B
static constexpr int OFF_W2   = 512;             // 512 B
static constexpr int OFF_PART = 1024;            // 1024 B
static constexpr int OFF_A0   = 2048;            // A fp16 ping-pong
static constexpr int OFF_A1   = OFF_A0 + TILE;
static constexpr int OFF_BB0  = OFF_A1 + TILE;   // B fp16 ping-pong
static constexpr int OFF_BB1  = OFF_BB0 + TILE;
static constexpr int SMEM_BYTES = OFF_BB1 + TILE;   // 75776 -> 3 CTAs/SM
// epilogue scratch ALIASES the A0 tile (dead after mainloop)
static constexpr int OFF_SCR  = OFF_A0;

__global__ void __launch_bounds__(256, 3)
gemm1_kernel(const float* __restrict__ feats, const float* __restrict__ b1,
             const float* __restrict__ w2, const float* __restrict__ b2,
             const int* __restrict__ mask) {
    extern __shared__ char dsm[];
    uint32_t sb = smem_u32(dsm);
    float* b1s  = (float*)(dsm + OFF_B1);
    float* w2s  = (float*)(dsm + OFF_W2);
    float* part = (float*)(dsm + OFF_PART);
    float* scr  = (float*)(dsm + OFF_SCR);       // aliases A0 (post-mainloop only)
    float* sa   = scr;                           // e values [128]

    int tid = threadIdx.x;
    int lane = tid & 31, warp = tid >> 5;
    int warp_m = warp >> 1, warp_n = warp & 1;   // 4 x 2 warp grid
    int m_base = warp_m * 32, n_base = warp_n * 64;

    if (tid < 128) { b1s[tid] = b1[tid]; w2s[tid] = w2[tid]; }

    const float* A0 = feats + (size_t)blockIdx.x * 128 * D_;

    // staging indices
    int ar = tid >> 4, ac4 = tid & 15;   // A: 8 iters x (row, float4-col)
    int bn = tid >> 3, bcu = tid & 7;    // B: 4 iters x (row, 16B-col)

    wmma::fragment<wmma::accumulator, 16, 16, 16, float> cfr[2][4];
    #pragma unroll
    for (int mi = 0; mi < 2; mi++)
        #pragma unroll
        for (int ni = 0; ni < 4; ni++)
            wmma::fill_fragment(cfr[mi][ni], 0.0f);

    auto ldg_a = [&](float4* av, int kc) {
        #pragma unroll
        for (int i = 0; i < 8; i++) {
            int r = ar + i * 16;
            av[i] = __ldg((const float4*)(A0 + (size_t)r * D_ + kc * 64) + ac4);
        }
    };
    auto sts_a = [&](const float4* av, int buf) {
        uint32_t base = sb + (buf ? OFF_A1 : OFF_A0);
        #pragma unroll
        for (int i = 0; i < 8; i++) {
            int r = ar + i * 16;
            uint32_t off = (uint32_t)(r * ROWB + ac4 * 8);
            __half2 h01 = __floats2half2_rn(av[i].x, av[i].y);
            __half2 h23 = __floats2half2_rn(av[i].z, av[i].w);
            asm volatile("st.shared.v2.b32 [%0], {%1, %2};"
                         :: "r"(base + off),
                            "r"(*(uint32_t*)&h01), "r"(*(uint32_t*)&h23) : "memory");
        }
    };
    auto cpa_b = [&](int kc, int buf) {
        uint32_t dbb = sb + (buf ? OFF_BB1 : OFF_BB0);
        #pragma unroll
        for (int i = 0; i < 4; i++) {
            int n = bn + i * 32;
            cpasync16(dbb + (uint32_t)(n * ROWB + bcu * 16),
                      g_w1t + (size_t)n * D_ + kc * 64 + bcu * 8);
        }
        asm volatile("cp.async.commit_group;" ::: "memory");
    };
    auto compute = [&](int buf) {
        const __half* As = (const __half*)(dsm + (buf ? OFF_A1 : OFF_A0));
        const __half* Bs = (const __half*)(dsm + (buf ? OFF_BB1 : OFF_BB0));
        #pragma unroll
        for (int ks = 0; ks < 4; ks++) {
            wmma::fragment<wmma::matrix_a, 16, 16, 16, __half, wmma::row_major> af[2];
            #pragma unroll
            for (int mi = 0; mi < 2; mi++) {
                const __half* pa = As + (size_t)(m_base + mi * 16) * ROWE + ks * 16;
                wmma::load_matrix_sync(af[mi], pa, ROWE);
            }
            #pragma unroll
            for (int ni = 0; ni < 4; ni++) {
                wmma::fragment<wmma::matrix_b, 16, 16, 16, __half, wmma::col_major> bf;
                const __half* pb = Bs + (size_t)(n_base + ni * 16) * ROWE + ks * 16;
                wmma::load_matrix_sync(bf, pb, ROWE);
                #pragma unroll
                for (int mi = 0; mi < 2; mi++)
                    wmma::mma_sync(cfr[mi][ni], af[mi], bf, cfr[mi][ni]);
            }
        }
    };

    // ---- prologue: stage chunk 0 into buffer 0 ----
    {
        float4 av[8];
        cpa_b(0, 0);
        ldg_a(av, 0);
        sts_a(av, 0);
        asm volatile("cp.async.wait_group 0;" ::: "memory");
    }
    __syncthreads();

    // ---- main loop: A and B double-buffered, ONE sync per chunk ----
    #pragma unroll 1
    for (int kc = 0; kc < 16; kc++) {
        int buf = kc & 1;
        float4 av[8];
        if (kc < 15) {
            ldg_a(av, kc + 1);
            cpa_b(kc + 1, buf ^ 1);
        }
        compute(buf);
        if (kc < 15) {
            sts_a(av, buf ^ 1);
            asm volatile("cp.async.wait_group 0;" ::: "memory");
        }
        __syncthreads();
    }

    // ---- epilogue part 1: p(row) = sum_j w2_j * tanh(c + b1_j) ----
    {
        float* ws = scr + warp * 256;
        int r16 = lane & 15, ch = (lane >> 4) * 8;
        float pacc[2] = {0.0f, 0.0f};
        #pragma unroll
        for (int mi = 0; mi < 2; mi++) {
            #pragma unroll
            for (int ni = 0; ni < 4; ni++) {
                wmma::store_matrix_sync(ws, cfr[mi][ni], 16, wmma::mem_row_major);
                __syncwarp();
                float s = 0.0f;
                #pragma unroll
                for (int j = 0; j < 8; j++) {
                    int col = n_base + ni * 16 + ch + j;
                    float v = ws[r16 * 16 + ch + j];
                    s += w2s[col] * tanhf(v + b1s[col]);
                }
                pacc[mi] += s;
                __syncwarp();
            }
        }
        #pragma unroll
        for (int mi = 0; mi < 2; mi++) {
            float tot = pacc[mi] + __shfl_xor_sync(0xffffffffu, pacc[mi], 16);
            if (lane < 16) {
                int row = m_base + mi * 16 + r16;
                part[row * 2 + warp_n] = tot;
            }
        }
    }
    __syncthreads();

    // ---- epilogue part 2: e = mask * exp(logit) ----
    int batch = blockIdx.x >> 6;
    int nidx = ((blockIdx.x & 63) << 7) + tid;
    if (tid < 128) {
        float logit = part[tid * 2] + part[tid * 2 + 1] + b2[0];
        int m = mask[(size_t)batch * N_ + nidx];
        float e = m ? expf(logit) : 0.0f;
        g_e[(size_t)batch * N_ + nidx] = e;
        sa[tid] = e;                 // scr region (A0 alias), safe post-mainloop
    }
    __syncthreads();

    // ---- epilogue part 3: unscaled weighted pool (tile L2-hot) ----
    {
        float4 acc0 = make_float4(0.f, 0.f, 0.f, 0.f);
        float4 acc1 = make_float4(0.f, 0.f, 0.f, 0.f);
        const float4* fp = (const float4*)A0 + tid;   // thread t owns float4-col t
        #pragma unroll 8
        for (int n = 0; n < 128; n += 2) {
            float a0 = sa[n], a1 = sa[n + 1];
            float4 v0 = __ldg(fp + (size_t)n * 256);
            float4 v1 = __ldg(fp + (size_t)(n + 1) * 256);
            acc0.x += a0 * v0.x; acc0.y += a0 * v0.y;
            acc0.z += a0 * v0.z; acc0.w += a0 * v0.w;
            acc1.x += a1 * v1.x; acc1.y += a1 * v1.y;
            acc1.z += a1 * v1.z; acc1.w += a1 * v1.w;
        }
        float4 acc = make_float4(acc0.x + acc1.x, acc0.y + acc1.y,
                                 acc0.z + acc1.z, acc0.w + acc1.w);
        ((float4*)(g_part + (size_t)blockIdx.x * D_))[tid] = acc;
    }
    __syncthreads();

    // ---- epilogue part 4: per-CTA e sum (tree over sa) ----
    #pragma unroll
    for (int o = 64; o > 0; o >>= 1) {
        if (tid < o) sa[tid] += sa[tid + o];
        __syncthreads();
    }
    if (tid == 0) g_erow[blockIdx.x] = sa[0];
}

// ---------------- kernel 2: attn = e / S  (S computed inline, deterministic) ----------------
__global__ void attn_kernel(float* __restrict__ attn) {
    __shared__ float red[64];
    int idx = blockIdx.x * 256 + threadIdx.x;    // 0..B*N-1
    int b = idx >> 13;
    int t = threadIdx.x;
    if (t < 64) red[t] = g_erow[b * CPB + t];
    __syncthreads();
    #pragma unroll
    for (int o = 32; o > 0; o >>= 1) {
        if (t < o) red[t] += red[t + o];
        __syncthreads();
    }
    float inv = 1.0f / fmaxf(red[0], 1e-8f);
    attn[idx] = g_e[idx] * inv;
}

// ---------------- kernel 3: pooled = (sum of partials) / S ----------------
__global__ void reduce_kernel(float* __restrict__ pooled) {
    __shared__ float red[64];
    int idx = blockIdx.x * 256 + threadIdx.x;    // 0..B*D-1
    int b = idx >> 10, d = idx & 1023;
    int t = threadIdx.x;
    if (t < 64) red[t] = g_erow[b * CPB + t];
    __syncthreads();
    #pragma unroll
    for (int o = 32; o > 0; o >>= 1) {
        if (t < o) red[t] += red[t + o];
        __syncthreads();
    }
    float inv = 1.0f / fmaxf(red[0], 1e-8f);
    float acc = 0.0f;
    #pragma unroll
    for (int s = 0; s < CPB; s++)
        acc += g_part[((size_t)b * CPB + s) * D_ + d];
    pooled[idx] = acc * inv;
}

// ---------------- kernel 4: final classifier ----------------
__global__ void final_kernel(const float* __restrict__ pooled,
                             const float* __restrict__ wc,
                             const float* __restrict__ bc,
                             float* __restrict__ logits) {
    __shared__ float red[256];
    int b = blockIdx.x, t = threadIdx.x;
    float acc = 0.0f;
    #pragma unroll
    for (int j = 0; j < 4; j++) {
        int d = t + j * 256;
        acc += pooled[(size_t)b * D_ + d] * wc[d];
    }
    red[t] = acc; __syncthreads();
    for (int o = 128; o > 0; o >>= 1) { if (t < o) red[t] += red[t + o]; __syncthreads(); }
    if (t == 0) logits[b] = red[0] + bc[0];
}

// ---------------- launch ----------------
extern "C" void kernel_launch(void* const* d_in, const int* in_sizes, int n_in,
                              void* d_out, int out_size) {
    const float* feats = (const float*)d_in[0];
    const int* mask = (const int*)d_in[1];       // jnp.bool_ -> int32
    const float* w1 = (const float*)d_in[2];
    const float* b1 = (const float*)d_in[3];
    const float* w2 = (const float*)d_in[4];
    const float* b2 = (const float*)d_in[5];
    const float* wc = (const float*)d_in[6];
    const float* bc = (const float*)d_in[7];

    float* out = (float*)d_out;
    float* out_logits = out;                 // [B]
    float* out_pooled = out + B_;            // [B, D]
    float* out_attn   = out + B_ + B_ * D_;  // [B, N]

    cudaFuncSetAttribute(gemm1_kernel,
                         cudaFuncAttributeMaxDynamicSharedMemorySize, SMEM_BYTES);

    prep_kernel<<<(H_ * D_) / 256, 256>>>(w1);
    gemm1_kernel<<<(B_ * N_) / 128, 256, SMEM_BYTES>>>(feats, b1, w2, b2, mask);
    attn_kernel<<<(B_ * N_) / 256, 256>>>(out_attn);
    reduce_kernel<<<(B_ * D_) / 256, 256>>>(out_pooled);
    final_kernel<<<B_, 256>>>(out_pooled, wc, bc, out_logits);
}

// round 12
// speedup vs baseline: 1.6374x; 1.6374x over previous
#include <cuda_runtime.h>
#include <cuda_fp16.h>
#include <mma.h>
#include <cstdint>
#include <math.h>

using namespace nvcuda;

#define B_ 32
#define N_ 8192
#define D_ 1024
#define H_ 128
#define CPB 64          // CTAs per batch in gemm1 (8192/128)

// ---------------- scratch (no cudaMalloc allowed) ----------------
__device__ __align__(16) unsigned short g_w1t[H_ * D_];   // fp16 W1^T [h][d]
__device__ __align__(16) float g_e[B_ * N_];              // mask*exp(logit)
__device__ __align__(16) float g_erow[B_ * CPB];          // per-CTA e sums
__device__ __align__(16) float g_part[B_ * CPB * D_];     // unscaled pooled partials (8 MB)

// ---------------- helpers ----------------
__device__ __forceinline__ uint32_t smem_u32(const void* p) {
    uint32_t a;
    asm("{ .reg .u64 t; cvta.to.shared.u64 t, %1; cvt.u32.u64 %0, t; }" : "=r"(a) : "l"(p));
    return a;
}
__device__ __forceinline__ void cpasync16(uint32_t dst, const void* src) {
    asm volatile("cp.async.cg.shared.global [%0], [%1], 16;"
                 :: "r"(dst), "l"(src) : "memory");
}

// ---------------- kernel 0: W1^T -> fp16 ----------------
__global__ void prep_kernel(const float* __restrict__ w1) {
    int idx = blockIdx.x * 256 + threadIdx.x;   // 0..H*D-1
    int h = idx >> 10, d = idx & 1023;
    g_w1t[idx] = __half_as_ushort(__float2half_rn(w1[(size_t)d * H_ + h]));
}

// ---------------- kernel 1: GEMM1 + tanh + fc2 + exp*mask + weighted pool ----------------
static constexpr int ROWE = 72;                  // row stride in fp16 elements
static constexpr int ROWB = 144;                 // row stride bytes (128 data + 16 pad)
static constexpr int TILE = 128 * ROWB;          // 18432 bytes per 128x64 tile
static constexpr int OFF_B1   = 0;               // 512 B
static constexpr int OFF_W2   = 512;             // 512 B
static constexpr int OFF_PART = 1024;            // 1024 B
static constexpr int OFF_SCR  = 2048;            // 8 warps * 256 floats = 8192 B
static constexpr int OFF_A0   = 10240;           // A fp16 ping-pong
static constexpr int OFF_A1   = OFF_A0 + TILE;
static constexpr int OFF_BB0  = OFF_A1 + TILE;   // B fp16 ping-pong
static constexpr int OFF_BB1  = OFF_BB0 + TILE;
static constexpr int SMEM_BYTES = OFF_BB1 + TILE;   // 83968 -> 2 CTAs/SM, no reg cap

__global__ void __launch_bounds__(256, 2)
gemm1_kernel(const float* __restrict__ feats, const float* __restrict__ b1,
             const float* __restrict__ w2, const float* __restrict__ b2,
             const int* __restrict__ mask) {
    extern __shared__ char dsm[];
    uint32_t sb = smem_u32(dsm);
    float* b1s  = (float*)(dsm + OFF_B1);
    float* w2s  = (float*)(dsm + OFF_W2);
    float* part = (float*)(dsm + OFF_PART);
    float* scr  = (float*)(dsm + OFF_SCR);
    float* sa   = scr;                            // e values [128] (post-epilogue reuse)

    int tid = threadIdx.x;
    int lane = tid & 31, warp = tid >> 5;
    int warp_m = warp >> 1, warp_n = warp & 1;   // 4 x 2 warp grid
    int m_base = warp_m * 32, n_base = warp_n * 64;

    if (tid < 128) { b1s[tid] = b1[tid]; w2s[tid] = w2[tid]; }

    const float* A0 = feats + (size_t)blockIdx.x * 128 * D_;

    // staging indices
    int ar = tid >> 4, ac4 = tid & 15;   // A: 8 iters x (row, float4-col)
    int bn = tid >> 3, bcu = tid & 7;    // B: 4 iters x (row, 16B-col)

    wmma::fragment<wmma::accumulator, 16, 16, 16, float> cfr[2][4];
    #pragma unroll
    for (int mi = 0; mi < 2; mi++)
        #pragma unroll
        for (int ni = 0; ni < 4; ni++)
            wmma::fill_fragment(cfr[mi][ni], 0.0f);

    auto ldg_a = [&](float4* av, int kc) {
        #pragma unroll
        for (int i = 0; i < 8; i++) {
            int r = ar + i * 16;
            av[i] = __ldg((const float4*)(A0 + (size_t)r * D_ + kc * 64) + ac4);
        }
    };
    auto sts_a = [&](const float4* av, int buf) {
        uint32_t base = sb + (buf ? OFF_A1 : OFF_A0);
        #pragma unroll
        for (int i = 0; i < 8; i++) {
            int r = ar + i * 16;
            uint32_t off = (uint32_t)(r * ROWB + ac4 * 8);
            __half2 h01 = __floats2half2_rn(av[i].x, av[i].y);
            __half2 h23 = __floats2half2_rn(av[i].z, av[i].w);
            asm volatile("st.shared.v2.b32 [%0], {%1, %2};"
                         :: "r"(base + off),
                            "r"(*(uint32_t*)&h01), "r"(*(uint32_t*)&h23) : "memory");
        }
    };
    auto cpa_b = [&](int kc, int buf) {
        uint32_t dbb = sb + (buf ? OFF_BB1 : OFF_BB0);
        #pragma unroll
        for (int i = 0; i < 4; i++) {
            int n = bn + i * 32;
            cpasync16(dbb + (uint32_t)(n * ROWB + bcu * 16),
                      g_w1t + (size_t)n * D_ + kc * 64 + bcu * 8);
        }
        asm volatile("cp.async.commit_group;" ::: "memory");
    };
    auto compute = [&](int buf) {
        const __half* As = (const __half*)(dsm + (buf ? OFF_A1 : OFF_A0));
        const __half* Bs = (const __half*)(dsm + (buf ? OFF_BB1 : OFF_BB0));
        #pragma unroll
        for (int ks = 0; ks < 4; ks++) {
            wmma::fragment<wmma::matrix_a, 16, 16, 16, __half, wmma::row_major> af[2];
            #pragma unroll
            for (int mi = 0; mi < 2; mi++) {
                const __half* pa = As + (size_t)(m_base + mi * 16) * ROWE + ks * 16;
                wmma::load_matrix_sync(af[mi], pa, ROWE);
            }
            #pragma unroll
            for (int ni = 0; ni < 4; ni++) {
                wmma::fragment<wmma::matrix_b, 16, 16, 16, __half, wmma::col_major> bf;
                const __half* pb = Bs + (size_t)(n_base + ni * 16) * ROWE + ks * 16;
                wmma::load_matrix_sync(bf, pb, ROWE);
                #pragma unroll
                for (int mi = 0; mi < 2; mi++)
                    wmma::mma_sync(cfr[mi][ni], af[mi], bf, cfr[mi][ni]);
            }
        }
    };

    // ---- prologue: stage chunk 0 into buffer 0 ----
    {
        float4 av[8];
        cpa_b(0, 0);
        ldg_a(av, 0);
        sts_a(av, 0);
        asm volatile("cp.async.wait_group 0;" ::: "memory");
    }
    __syncthreads();

    // ---- main loop: A and B double-buffered, ONE sync per chunk ----
    #pragma unroll 1
    for (int kc = 0; kc < 16; kc++) {
        int buf = kc & 1;
        float4 av[8];
        if (kc < 15) {
            ldg_a(av, kc + 1);
            cpa_b(kc + 1, buf ^ 1);
        }
        compute(buf);
        if (kc < 15) {
            sts_a(av, buf ^ 1);
            asm volatile("cp.async.wait_group 0;" ::: "memory");
        }
        __syncthreads();
    }

    // ---- epilogue part 1: p(row) = sum_j w2_j * tanh(c + b1_j) ----
    {
        float* ws = scr + warp * 256;
        int r16 = lane & 15, ch = (lane >> 4) * 8;
        float pacc[2] = {0.0f, 0.0f};
        #pragma unroll
        for (int mi = 0; mi < 2; mi++) {
            #pragma unroll
            for (int ni = 0; ni < 4; ni++) {
                wmma::store_matrix_sync(ws, cfr[mi][ni], 16, wmma::mem_row_major);
                __syncwarp();
                float s = 0.0f;
                #pragma unroll
                for (int j = 0; j < 8; j++) {
                    int col = n_base + ni * 16 + ch + j;
                    float v = ws[r16 * 16 + ch + j];
                    s += w2s[col] * tanhf(v + b1s[col]);
                }
                pacc[mi] += s;
                __syncwarp();
            }
        }
        #pragma unroll
        for (int mi = 0; mi < 2; mi++) {
            float tot = pacc[mi] + __shfl_xor_sync(0xffffffffu, pacc[mi], 16);
            if (lane < 16) {
                int row = m_base + mi * 16 + r16;
                part[row * 2 + warp_n] = tot;
            }
        }
    }
    __syncthreads();

    // ---- epilogue part 2: e = mask * exp(logit) ----
    int batch = blockIdx.x >> 6;
    int nidx = ((blockIdx.x & 63) << 7) + tid;
    if (tid < 128) {
        float logit = part[tid * 2] + part[tid * 2 + 1] + b2[0];
        int m = mask[(size_t)batch * N_ + nidx];
        float e = m ? expf(logit) : 0.0f;
        g_e[(size_t)batch * N_ + nidx] = e;
        sa[tid] = e;
    }
    __syncthreads();

    // ---- epilogue part 3: unscaled weighted pool (tile L2-hot), 2 acc chains ----
    {
        float4 acc0 = make_float4(0.f, 0.f, 0.f, 0.f);
        float4 acc1 = make_float4(0.f, 0.f, 0.f, 0.f);
        const float4* fp = (const float4*)A0 + tid;   // thread t owns float4-col t
        #pragma unroll 8
        for (int n = 0; n < 128; n += 2) {
            float a0 = sa[n], a1 = sa[n + 1];
            float4 v0 = __ldg(fp + (size_t)n * 256);
            float4 v1 = __ldg(fp + (size_t)(n + 1) * 256);
            acc0.x += a0 * v0.x; acc0.y += a0 * v0.y;
            acc0.z += a0 * v0.z; acc0.w += a0 * v0.w;
            acc1.x += a1 * v1.x; acc1.y += a1 * v1.y;
            acc1.z += a1 * v1.z; acc1.w += a1 * v1.w;
        }
        float4 acc = make_float4(acc0.x + acc1.x, acc0.y + acc1.y,
                                 acc0.z + acc1.z, acc0.w + acc1.w);
        ((float4*)(g_part + (size_t)blockIdx.x * D_))[tid] = acc;
    }
    __syncthreads();

    // ---- epilogue part 4: per-CTA e sum (tree over sa) ----
    #pragma unroll
    for (int o = 64; o > 0; o >>= 1) {
        if (tid < o) sa[tid] += sa[tid + o];
        __syncthreads();
    }
    if (tid == 0) g_erow[blockIdx.x] = sa[0];
}

// ---------------- kernel 2: attn = e / S  (S computed inline, deterministic) ----------------
__global__ void attn_kernel(float* __restrict__ attn) {
    __shared__ float red[64];
    int idx = blockIdx.x * 256 + threadIdx.x;    // 0..B*N-1
    int b = idx >> 13;
    int t = threadIdx.x;
    if (t < 64) red[t] = g_erow[b * CPB + t];
    __syncthreads();
    #pragma unroll
    for (int o = 32; o > 0; o >>= 1) {
        if (t < o) red[t] += red[t + o];
        __syncthreads();
    }
    float inv = 1.0f / fmaxf(red[0], 1e-8f);
    attn[idx] = g_e[idx] * inv;
}

// ---------------- kernel 3: pooled = (sum of partials) / S ----------------
__global__ void reduce_kernel(float* __restrict__ pooled) {
    __shared__ float red[64];
    int idx = blockIdx.x * 256 + threadIdx.x;    // 0..B*D-1
    int b = idx >> 10, d = idx & 1023;
    int t = threadIdx.x;
    if (t < 64) red[t] = g_erow[b * CPB + t];
    __syncthreads();
    #pragma unroll
    for (int o = 32; o > 0; o >>= 1) {
        if (t < o) red[t] += red[t + o];
        __syncthreads();
    }
    float inv = 1.0f / fmaxf(red[0], 1e-8f);
    float acc = 0.0f;
    #pragma unroll
    for (int s = 0; s < CPB; s++)
        acc += g_part[((size_t)b * CPB + s) * D_ + d];
    pooled[idx] = acc * inv;
}

// ---------------- kernel 4: final classifier ----------------
__global__ void final_kernel(const float* __restrict__ pooled,
                             const float* __restrict__ wc,
                             const float* __restrict__ bc,
                             float* __restrict__ logits) {
    __shared__ float red[256];
    int b = blockIdx.x, t = threadIdx.x;
    float acc = 0.0f;
    #pragma unroll
    for (int j = 0; j < 4; j++) {
        int d = t + j * 256;
        acc += pooled[(size_t)b * D_ + d] * wc[d];
    }
    red[t] = acc; __syncthreads();
    for (int o = 128; o > 0; o >>= 1) { if (t < o) red[t] += red[t + o]; __syncthreads(); }
    if (t == 0) logits[b] = red[0] + bc[0];
}

// ---------------- launch ----------------
extern "C" void kernel_launch(void* const* d_in, const int* in_sizes, int n_in,
                              void* d_out, int out_size) {
    const float* feats = (const float*)d_in[0];
    const int* mask = (const int*)d_in[1];       // jnp.bool_ -> int32
    const float* w1 = (const float*)d_in[2];
    const float* b1 = (const float*)d_in[3];
    const float* w2 = (const float*)d_in[4];
    const float* b2 = (const float*)d_in[5];
    const float* wc = (const float*)d_in[6];
    const float* bc = (const float*)d_in[7];

    float* out = (float*)d_out;
    float* out_logits = out;                 // [B]
    float* out_pooled = out + B_;            // [B, D]
    float* out_attn   = out + B_ + B_ * D_;  // [B, N]

    cudaFuncSetAttribute(gemm1_kernel,
                         cudaFuncAttributeMaxDynamicSharedMemorySize, SMEM_BYTES);

    prep_kernel<<<(H_ * D_) / 256, 256>>>(w1);
    gemm1_kernel<<<(B_ * N_) / 128, 256, SMEM_BYTES>>>(feats, b1, w2, b2, mask);
    attn_kernel<<<(B_ * N_) / 256, 256>>>(out_attn);
    reduce_kernel<<<(B_ * D_) / 256, 256>>>(out_pooled);
    final_kernel<<<B_, 256>>>(out_pooled, wc, bc, out_logits);
}

// round 13
// speedup vs baseline: 2.1999x; 1.3436x over previous
#include <cuda_runtime.h>
#include <cuda_fp16.h>
#include <mma.h>
#include <cstdint>
#include <math.h>

using namespace nvcuda;

#define B_ 32
#define N_ 8192
#define D_ 1024
#define H_ 128
#define CPB 64          // CTAs per batch in gemm1 (8192/128)

// ---------------- scratch (no cudaMalloc allowed) ----------------
__device__ __align__(16) unsigned short g_w1t[H_ * D_];   // fp16 W1^T [h][d]
__device__ __align__(16) float g_e[B_ * N_];              // mask*exp(logit)
__device__ __align__(16) float g_erow[B_ * CPB];          // per-CTA e sums
__device__ __align__(16) float g_part[B_ * CPB * D_];     // unscaled pooled partials (8 MB)

// ---------------- helpers ----------------
__device__ __forceinline__ uint32_t smem_u32(const void* p) {
    uint32_t a;
    asm("{ .reg .u64 t; cvta.to.shared.u64 t, %1; cvt.u32.u64 %0, t; }" : "=r"(a) : "l"(p));
    return a;
}
__device__ __forceinline__ void cpasync16(uint32_t dst, const void* src) {
    asm volatile("cp.async.cg.shared.global [%0], [%1], 16;"
                 :: "r"(dst), "l"(src) : "memory");
}

// ---------------- kernel 0: W1^T -> fp16 ----------------
__global__ void prep_kernel(const float* __restrict__ w1) {
    int idx = blockIdx.x * 256 + threadIdx.x;   // 0..H*D-1
    int h = idx >> 10, d = idx & 1023;
    g_w1t[idx] = __half_as_ushort(__float2half_rn(w1[(size_t)d * H_ + h]));
}

// ---------------- kernel 1: GEMM1 + tanh + fc2 + exp*mask + weighted pool ----------------
static constexpr int ROWE = 72;                  // row stride in fp16 elements
static constexpr int ROWB = 144;                 // row stride bytes (128 data + 16 pad)
static constexpr int TILE = 128 * ROWB;          // 18432 bytes per 128x64 tile
static constexpr int OFF_B1   = 0;               // 512 B
static constexpr int OFF_W2   = 512;             // 512 B
static constexpr int OFF_PART = 1024;            // 1024 B
static constexpr int OFF_SCR  = 2048;            // 8 warps * 256 floats = 8192 B
static constexpr int OFF_A0   = 10240;           // A fp16 ping-pong
static constexpr int OFF_A1   = OFF_A0 + TILE;
static constexpr int OFF_BB0  = OFF_A1 + TILE;   // B fp16 ping-pong
static constexpr int OFF_BB1  = OFF_BB0 + TILE;
static constexpr int SMEM_BYTES = OFF_BB1 + TILE;   // 83968

__global__ void __launch_bounds__(256, 2)
gemm1_kernel(const float* __restrict__ feats, const float* __restrict__ b1,
             const float* __restrict__ w2, const float* __restrict__ b2,
             const int* __restrict__ mask) {
    extern __shared__ char dsm[];
    uint32_t sb = smem_u32(dsm);
    float* b1s  = (float*)(dsm + OFF_B1);
    float* w2s  = (float*)(dsm + OFF_W2);
    float* part = (float*)(dsm + OFF_PART);
    float* scr  = (float*)(dsm + OFF_SCR);
    float* sa   = scr;                            // e values [128] (post-epilogue reuse)

    int tid = threadIdx.x;
    int lane = tid & 31, warp = tid >> 5;
    int warp_m = warp >> 1, warp_n = warp & 1;   // 4 x 2 warp grid
    int m_base = warp_m * 32, n_base = warp_n * 64;

    if (tid < 128) { b1s[tid] = b1[tid]; w2s[tid] = w2[tid]; }

    const float* A0 = feats + (size_t)blockIdx.x * 128 * D_;

    // staging indices
    int ar = tid >> 4, ac4 = tid & 15;   // A: 8 iters x (row, float4-col)
    int bn = tid >> 3, bcu = tid & 7;    // B: 4 iters x (row, 16B-col)

    wmma::fragment<wmma::accumulator, 16, 16, 16, float> cfr[2][4];
    #pragma unroll
    for (int mi = 0; mi < 2; mi++)
        #pragma unroll
        for (int ni = 0; ni < 4; ni++)
            wmma::fill_fragment(cfr[mi][ni], 0.0f);

    auto ldg_a = [&](float4* av, int kc) {
        #pragma unroll
        for (int i = 0; i < 8; i++) {
            int r = ar + i * 16;
            av[i] = __ldg((const float4*)(A0 + (size_t)r * D_ + kc * 64) + ac4);
        }
    };
    auto sts_a = [&](const float4* av, int buf) {
        uint32_t base = sb + (buf ? OFF_A1 : OFF_A0);
        #pragma unroll
        for (int i = 0; i < 8; i++) {
            int r = ar + i * 16;
            uint32_t off = (uint32_t)(r * ROWB + ac4 * 8);
            __half2 h01 = __floats2half2_rn(av[i].x, av[i].y);
            __half2 h23 = __floats2half2_rn(av[i].z, av[i].w);
            asm volatile("st.shared.v2.b32 [%0], {%1, %2};"
                         :: "r"(base + off),
                            "r"(*(uint32_t*)&h01), "r"(*(uint32_t*)&h23) : "memory");
        }
    };
    auto cpa_b = [&](int kc, int buf) {
        uint32_t dbb = sb + (buf ? OFF_BB1 : OFF_BB0);
        #pragma unroll
        for (int i = 0; i < 4; i++) {
            int n = bn + i * 32;
            cpasync16(dbb + (uint32_t)(n * ROWB + bcu * 16),
                      g_w1t + (size_t)n * D_ + kc * 64 + bcu * 8);
        }
        asm volatile("cp.async.commit_group;" ::: "memory");
    };
    auto compute = [&](int buf) {
        const __half* As = (const __half*)(dsm + (buf ? OFF_A1 : OFF_A0));
        const __half* Bs = (const __half*)(dsm + (buf ? OFF_BB1 : OFF_BB0));
        #pragma unroll
        for (int ks = 0; ks < 4; ks++) {
            wmma::fragment<wmma::matrix_a, 16, 16, 16, __half, wmma::row_major> af[2];
            #pragma unroll
            for (int mi = 0; mi < 2; mi++) {
                const __half* pa = As + (size_t)(m_base + mi * 16) * ROWE + ks * 16;
                wmma::load_matrix_sync(af[mi], pa, ROWE);
            }
            #pragma unroll
            for (int ni = 0; ni < 4; ni++) {
                wmma::fragment<wmma::matrix_b, 16, 16, 16, __half, wmma::col_major> bf;
                const __half* pb = Bs + (size_t)(n_base + ni * 16) * ROWE + ks * 16;
                wmma::load_matrix_sync(bf, pb, ROWE);
                #pragma unroll
                for (int mi = 0; mi < 2; mi++)
                    wmma::mma_sync(cfr[mi][ni], af[mi], bf, cfr[mi][ni]);
            }
        }
    };

    // ---- prologue: stage chunk 0 into buffer 0 ----
    {
        float4 av[8];
        cpa_b(0, 0);
        ldg_a(av, 0);
        sts_a(av, 0);
        asm volatile("cp.async.wait_group 0;" ::: "memory");
    }
    __syncthreads();

    // ---- main loop: A and B double-buffered, ONE sync per chunk ----
    #pragma unroll 1
    for (int kc = 0; kc < 16; kc++) {
        int buf = kc & 1;
        float4 av[8];
        if (kc < 15) {
            ldg_a(av, kc + 1);
            cpa_b(kc + 1, buf ^ 1);
        }
        compute(buf);
        if (kc < 15) {
            sts_a(av, buf ^ 1);
            asm volatile("cp.async.wait_group 0;" ::: "memory");
        }
        __syncthreads();
    }

    // ---- epilogue part 1: p(row) = sum_j w2_j * tanh(c + b1_j) ----
    {
        float* ws = scr + warp * 256;
        int r16 = lane & 15, ch = (lane >> 4) * 8;
        float pacc[2] = {0.0f, 0.0f};
        #pragma unroll
        for (int mi = 0; mi < 2; mi++) {
            #pragma unroll
            for (int ni = 0; ni < 4; ni++) {
                wmma::store_matrix_sync(ws, cfr[mi][ni], 16, wmma::mem_row_major);
                __syncwarp();
                float s = 0.0f;
                #pragma unroll
                for (int j = 0; j < 8; j++) {
                    int col = n_base + ni * 16 + ch + j;
                    float v = ws[r16 * 16 + ch + j];
                    s += w2s[col] * tanhf(v + b1s[col]);
                }
                pacc[mi] += s;
                __syncwarp();
            }
        }
        #pragma unroll
        for (int mi = 0; mi < 2; mi++) {
            float tot = pacc[mi] + __shfl_xor_sync(0xffffffffu, pacc[mi], 16);
            if (lane < 16) {
                int row = m_base + mi * 16 + r16;
                part[row * 2 + warp_n] = tot;
            }
        }
    }
    __syncthreads();

    // ---- epilogue part 2: e = mask * exp(logit) ----
    int batch = blockIdx.x >> 6;
    int nidx = ((blockIdx.x & 63) << 7) + tid;
    if (tid < 128) {
        float logit = part[tid * 2] + part[tid * 2 + 1] + b2[0];
        int m = mask[(size_t)batch * N_ + nidx];
        float e = m ? expf(logit) : 0.0f;
        g_e[(size_t)batch * N_ + nidx] = e;
        sa[tid] = e;                 // scr region, safe after part-1 done
    }
    __syncthreads();

    // ---- epilogue part 3: unscaled weighted pool; tile is L2-hot ----
    {
        float4 acc = make_float4(0.f, 0.f, 0.f, 0.f);
        const float4* fp = (const float4*)A0 + tid;   // thread t owns float4-col t
        #pragma unroll 8
        for (int n = 0; n < 128; n++) {
            float a = sa[n];
            float4 v = __ldg(fp + (size_t)n * 256);
            acc.x += a * v.x; acc.y += a * v.y; acc.z += a * v.z; acc.w += a * v.w;
        }
        ((float4*)(g_part + (size_t)blockIdx.x * D_))[tid] = acc;
    }
    __syncthreads();

    // ---- epilogue part 4: per-CTA e sum (tree over sa) ----
    #pragma unroll
    for (int o = 64; o > 0; o >>= 1) {
        if (tid < o) sa[tid] += sa[tid + o];
        __syncthreads();
    }
    if (tid == 0) g_erow[blockIdx.x] = sa[0];
}

// ---------------- kernel 2: attn = e / S  (S computed inline, deterministic) ----------------
__global__ void attn_kernel(float* __restrict__ attn) {
    __shared__ float red[64];
    int idx = blockIdx.x * 256 + threadIdx.x;    // 0..B*N-1
    int b = idx >> 13;
    int t = threadIdx.x;
    if (t < 64) red[t] = g_erow[b * CPB + t];
    __syncthreads();
    #pragma unroll
    for (int o = 32; o > 0; o >>= 1) {
        if (t < o) red[t] += red[t + o];
        __syncthreads();
    }
    float inv = 1.0f / fmaxf(red[0], 1e-8f);
    attn[idx] = g_e[idx] * inv;
}

// ---------------- kernel 3: pooled = (sum of partials) / S ----------------
__global__ void reduce_kernel(float* __restrict__ pooled) {
    __shared__ float red[64];
    int idx = blockIdx.x * 256 + threadIdx.x;    // 0..B*D-1
    int b = idx >> 10, d = idx & 1023;
    int t = threadIdx.x;
    if (t < 64) red[t] = g_erow[b * CPB + t];
    __syncthreads();
    #pragma unroll
    for (int o = 32; o > 0; o >>= 1) {
        if (t < o) red[t] += red[t + o];
        __syncthreads();
    }
    float inv = 1.0f / fmaxf(red[0], 1e-8f);
    float acc = 0.0f;
    #pragma unroll
    for (int s = 0; s < CPB; s++)
        acc += g_part[((size_t)b * CPB + s) * D_ + d];
    pooled[idx] = acc * inv;
}

// ---------------- kernel 4: final classifier ----------------
__global__ void final_kernel(const float* __restrict__ pooled,
                             const float* __restrict__ wc,
                             const float* __restrict__ bc,
                             float* __restrict__ logits) {
    __shared__ float red[256];
    int b = blockIdx.x, t = threadIdx.x;
    float acc = 0.0f;
    #pragma unroll
    for (int j = 0; j < 4; j++) {
        int d = t + j * 256;
        acc += pooled[(size_t)b * D_ + d] * wc[d];
    }
    red[t] = acc; __syncthreads();
    for (int o = 128; o > 0; o >>= 1) { if (t < o) red[t] += red[t + o]; __syncthreads(); }
    if (t == 0) logits[b] = red[0] + bc[0];
}

// ---------------- launch ----------------
extern "C" void kernel_launch(void* const* d_in, const int* in_sizes, int n_in,
                              void* d_out, int out_size) {
    const float* feats = (const float*)d_in[0];
    const int* mask = (const int*)d_in[1];       // jnp.bool_ -> int32
    const float* w1 = (const float*)d_in[2];
    const float* b1 = (const float*)d_in[3];
    const float* w2 = (const float*)d_in[4];
    const float* b2 = (const float*)d_in[5];
    const float* wc = (const float*)d_in[6];
    const float* bc = (const float*)d_in[7];

    float* out = (float*)d_out;
    float* out_logits = out;                 // [B]
    float* out_pooled = out + B_;            // [B, D]
    float* out_attn   = out + B_ + B_ * D_;  // [B, N]

    cudaFuncSetAttribute(gemm1_kernel,
                         cudaFuncAttributeMaxDynamicSharedMemorySize, SMEM_BYTES);

    prep_kernel<<<(H_ * D_) / 256, 256>>>(w1);
    gemm1_kernel<<<(B_ * N_) / 128, 256, SMEM_BYTES>>>(feats, b1, w2, b2, mask);
    attn_kernel<<<(B_ * N_) / 256, 256>>>(out_attn);
    reduce_kernel<<<(B_ * D_) / 256, 256>>>(out_pooled);
    final_kernel<<<B_, 256>>>(out_pooled, wc, bc, out_logits);
}

// round 14
// speedup vs baseline: 2.2112x; 1.0051x over previous
#include <cuda_runtime.h>
#include <cuda_fp16.h>
#include <mma.h>
#include <cstdint>
#include <math.h>

using namespace nvcuda;

#define B_ 32
#define N_ 8192
#define D_ 1024
#define H_ 128
#define CPB 64          // CTAs per batch in gemm1 (8192/128)

// ---------------- scratch (no cudaMalloc allowed) ----------------
__device__ __align__(16) unsigned short g_w1t[H_ * D_];   // fp16 W1^T [h][d]
__device__ __align__(16) float g_e[B_ * N_];              // mask*exp(logit)
__device__ __align__(16) float g_erow[B_ * CPB];          // per-CTA e sums
__device__ __align__(16) float g_part[B_ * CPB * D_];     // unscaled pooled partials (8 MB)

// ---------------- helpers ----------------
__device__ __forceinline__ uint32_t smem_u32(const void* p) {
    uint32_t a;
    asm("{ .reg .u64 t; cvta.to.shared.u64 t, %1; cvt.u32.u64 %0, t; }" : "=r"(a) : "l"(p));
    return a;
}
__device__ __forceinline__ void cpasync16(uint32_t dst, const void* src) {
    asm volatile("cp.async.cg.shared.global [%0], [%1], 16;"
                 :: "r"(dst), "l"(src) : "memory");
}

// ---------------- kernel 0: W1^T -> fp16 ----------------
__global__ void prep_kernel(const float* __restrict__ w1) {
    int idx = blockIdx.x * 256 + threadIdx.x;   // 0..H*D-1
    int h = idx >> 10, d = idx & 1023;
    g_w1t[idx] = __half_as_ushort(__float2half_rn(w1[(size_t)d * H_ + h]));
}

// ---------------- kernel 1: GEMM1 + tanh + fc2 + exp*mask + weighted pool ----------------
static constexpr int ROWE = 72;                  // row stride in fp16 elements
static constexpr int ROWB = 144;                 // row stride bytes (128 data + 16 pad)
static constexpr int TILE = 128 * ROWB;          // 18432 bytes per 128x64 tile
static constexpr int OFF_B1   = 0;               // 512 B
static constexpr int OFF_W2   = 512;             // 512 B
static constexpr int OFF_PART = 1024;            // 1024 B
static constexpr int OFF_SCR  = 2048;            // 8 warps * 256 floats = 8192 B
static constexpr int OFF_A0   = 10240;           // A fp16 ping-pong
static constexpr int OFF_A1   = OFF_A0 + TILE;
static constexpr int OFF_BB0  = OFF_A1 + TILE;   // B fp16 ping-pong
static constexpr int OFF_BB1  = OFF_BB0 + TILE;
static constexpr int SMEM_BYTES = OFF_BB1 + TILE;   // 83968

__global__ void __launch_bounds__(256, 2)
gemm1_kernel(const float* __restrict__ feats, const float* __restrict__ b1,
             const float* __restrict__ w2, const float* __restrict__ b2,
             const int* __restrict__ mask) {
    extern __shared__ char dsm[];
    uint32_t sb = smem_u32(dsm);
    float* b1s  = (float*)(dsm + OFF_B1);
    float* w2s  = (float*)(dsm + OFF_W2);
    float* part = (float*)(dsm + OFF_PART);
    float* scr  = (float*)(dsm + OFF_SCR);
    float* sa   = scr;                            // e values [128] (post-epilogue reuse)

    int tid = threadIdx.x;
    int lane = tid & 31, warp = tid >> 5;
    int warp_m = warp >> 1, warp_n = warp & 1;   // 4 x 2 warp grid
    int m_base = warp_m * 32, n_base = warp_n * 64;

    if (tid < 128) { b1s[tid] = b1[tid]; w2s[tid] = w2[tid]; }

    const float* A0 = feats + (size_t)blockIdx.x * 128 * D_;

    // staging indices
    int ar = tid >> 4, ac4 = tid & 15;   // A: 8 iters x (row, float4-col)
    int bn = tid >> 3, bcu = tid & 7;    // B: 4 iters x (row, 16B-col)

    wmma::fragment<wmma::accumulator, 16, 16, 16, float> cfr[2][4];
    #pragma unroll
    for (int mi = 0; mi < 2; mi++)
        #pragma unroll
        for (int ni = 0; ni < 4; ni++)
            wmma::fill_fragment(cfr[mi][ni], 0.0f);

    auto ldg_a = [&](float4* av, int kc) {
        #pragma unroll
        for (int i = 0; i < 8; i++) {
            int r = ar + i * 16;
            av[i] = __ldg((const float4*)(A0 + (size_t)r * D_ + kc * 64) + ac4);
        }
    };
    auto sts_a = [&](const float4* av, int buf) {
        uint32_t base = sb + (buf ? OFF_A1 : OFF_A0);
        #pragma unroll
        for (int i = 0; i < 8; i++) {
            int r = ar + i * 16;
            uint32_t off = (uint32_t)(r * ROWB + ac4 * 8);
            __half2 h01 = __floats2half2_rn(av[i].x, av[i].y);
            __half2 h23 = __floats2half2_rn(av[i].z, av[i].w);
            asm volatile("st.shared.v2.b32 [%0], {%1, %2};"
                         :: "r"(base + off),
                            "r"(*(uint32_t*)&h01), "r"(*(uint32_t*)&h23) : "memory");
        }
    };
    auto cpa_b = [&](int kc, int buf) {
        uint32_t dbb = sb + (buf ? OFF_BB1 : OFF_BB0);
        #pragma unroll
        for (int i = 0; i < 4; i++) {
            int n = bn + i * 32;
            cpasync16(dbb + (uint32_t)(n * ROWB + bcu * 16),
                      g_w1t + (size_t)n * D_ + kc * 64 + bcu * 8);
        }
        asm volatile("cp.async.commit_group;" ::: "memory");
    };
    auto compute = [&](int buf) {
        const __half* As = (const __half*)(dsm + (buf ? OFF_A1 : OFF_A0));
        const __half* Bs = (const __half*)(dsm + (buf ? OFF_BB1 : OFF_BB0));
        #pragma unroll
        for (int ks = 0; ks < 4; ks++) {
            wmma::fragment<wmma::matrix_a, 16, 16, 16, __half, wmma::row_major> af[2];
            #pragma unroll
            for (int mi = 0; mi < 2; mi++) {
                const __half* pa = As + (size_t)(m_base + mi * 16) * ROWE + ks * 16;
                wmma::load_matrix_sync(af[mi], pa, ROWE);
            }
            #pragma unroll
            for (int ni = 0; ni < 4; ni++) {
                wmma::fragment<wmma::matrix_b, 16, 16, 16, __half, wmma::col_major> bf;
                const __half* pb = Bs + (size_t)(n_base + ni * 16) * ROWE + ks * 16;
                wmma::load_matrix_sync(bf, pb, ROWE);
                #pragma unroll
                for (int mi = 0; mi < 2; mi++)
                    wmma::mma_sync(cfr[mi][ni], af[mi], bf, cfr[mi][ni]);
            }
        }
    };

    // ---- prologue: stage chunk 0 into buffer 0 ----
    {
        float4 av[8];
        cpa_b(0, 0);
        ldg_a(av, 0);
        sts_a(av, 0);
        asm volatile("cp.async.wait_group 0;" ::: "memory");
    }
    __syncthreads();

    // ---- main loop: A and B double-buffered, ONE sync per chunk ----
    #pragma unroll 1
    for (int kc = 0; kc < 16; kc++) {
        int buf = kc & 1;
        float4 av[8];
        if (kc < 15) {
            ldg_a(av, kc + 1);
            cpa_b(kc + 1, buf ^ 1);
        }
        compute(buf);
        if (kc < 15) {
            sts_a(av, buf ^ 1);
            asm volatile("cp.async.wait_group 0;" ::: "memory");
        }
        __syncthreads();
    }

    // ---- epilogue part 1: p(row) = sum_j w2_j * tanh(c + b1_j) ----
    {
        float* ws = scr + warp * 256;
        int r16 = lane & 15, ch = (lane >> 4) * 8;
        float pacc[2] = {0.0f, 0.0f};
        #pragma unroll
        for (int mi = 0; mi < 2; mi++) {
            #pragma unroll
            for (int ni = 0; ni < 4; ni++) {
                wmma::store_matrix_sync(ws, cfr[mi][ni], 16, wmma::mem_row_major);
                __syncwarp();
                float s = 0.0f;
                #pragma unroll
                for (int j = 0; j < 8; j++) {
                    int col = n_base + ni * 16 + ch + j;
                    float v = ws[r16 * 16 + ch + j];
                    s += w2s[col] * tanhf(v + b1s[col]);
                }
                pacc[mi] += s;
                __syncwarp();
            }
        }
        #pragma unroll
        for (int mi = 0; mi < 2; mi++) {
            float tot = pacc[mi] + __shfl_xor_sync(0xffffffffu, pacc[mi], 16);
            if (lane < 16) {
                int row = m_base + mi * 16 + r16;
                part[row * 2 + warp_n] = tot;
            }
        }
    }
    __syncthreads();

    // ---- epilogue part 2: e = mask * exp(logit) ----
    int batch = blockIdx.x >> 6;
    int nidx = ((blockIdx.x & 63) << 7) + tid;
    if (tid < 128) {
        float logit = part[tid * 2] + part[tid * 2 + 1] + b2[0];
        int m = mask[(size_t)batch * N_ + nidx];
        float e = m ? expf(logit) : 0.0f;
        g_e[(size_t)batch * N_ + nidx] = e;
        sa[tid] = e;                 // scr region, safe after part-1 done
    }
    __syncthreads();

    // ---- epilogue part 3: unscaled weighted pool; tile is L2-hot ----
    {
        float4 acc = make_float4(0.f, 0.f, 0.f, 0.f);
        const float4* fp = (const float4*)A0 + tid;   // thread t owns float4-col t
        #pragma unroll 8
        for (int n = 0; n < 128; n++) {
            float a = sa[n];
            float4 v = __ldg(fp + (size_t)n * 256);
            acc.x += a * v.x; acc.y += a * v.y; acc.z += a * v.z; acc.w += a * v.w;
        }
        ((float4*)(g_part + (size_t)blockIdx.x * D_))[tid] = acc;
    }
    __syncthreads();

    // ---- epilogue part 4: per-CTA e sum (tree over sa) ----
    #pragma unroll
    for (int o = 64; o > 0; o >>= 1) {
        if (tid < o) sa[tid] += sa[tid + o];
        __syncthreads();
    }
    if (tid == 0) g_erow[blockIdx.x] = sa[0];
}

// ---------------- kernel 2: fused tail — attn (blocks 0..1023) + pooled reduce (1024..1151) ----------------
__global__ void tail_kernel(float* __restrict__ attn, float* __restrict__ pooled) {
    __shared__ float red[64];
    int bid = blockIdx.x;
    int t = threadIdx.x;
    if (bid < 1024) {
        // attn: idx over B*N
        int idx = bid * 256 + t;
        int b = idx >> 13;
        if (t < 64) red[t] = g_erow[b * CPB + t];
        __syncthreads();
        #pragma unroll
        for (int o = 32; o > 0; o >>= 1) {
            if (t < o) red[t] += red[t + o];
            __syncthreads();
        }
        float inv = 1.0f / fmaxf(red[0], 1e-8f);
        attn[idx] = g_e[idx] * inv;
    } else {
        // reduce: idx over B*D
        int idx = (bid - 1024) * 256 + t;
        int b = idx >> 10, d = idx & 1023;
        if (t < 64) red[t] = g_erow[b * CPB + t];
        __syncthreads();
        #pragma unroll
        for (int o = 32; o > 0; o >>= 1) {
            if (t < o) red[t] += red[t + o];
            __syncthreads();
        }
        float inv = 1.0f / fmaxf(red[0], 1e-8f);
        float acc = 0.0f;
        #pragma unroll
        for (int s = 0; s < CPB; s++)
            acc += g_part[((size_t)b * CPB + s) * D_ + d];
        pooled[idx] = acc * inv;
    }
}

// ---------------- kernel 3: final classifier ----------------
__global__ void final_kernel(const float* __restrict__ pooled,
                             const float* __restrict__ wc,
                             const float* __restrict__ bc,
                             float* __restrict__ logits) {
    __shared__ float red[256];
    int b = blockIdx.x, t = threadIdx.x;
    float acc = 0.0f;
    #pragma unroll
    for (int j = 0; j < 4; j++) {
        int d = t + j * 256;
        acc += pooled[(size_t)b * D_ + d] * wc[d];
    }
    red[t] = acc; __syncthreads();
    for (int o = 128; o > 0; o >>= 1) { if (t < o) red[t] += red[t + o]; __syncthreads(); }
    if (t == 0) logits[b] = red[0] + bc[0];
}

// ---------------- launch ----------------
extern "C" void kernel_launch(void* const* d_in, const int* in_sizes, int n_in,
                              void* d_out, int out_size) {
    const float* feats = (const float*)d_in[0];
    const int* mask = (const int*)d_in[1];       // jnp.bool_ -> int32
    const float* w1 = (const float*)d_in[2];
    const float* b1 = (const float*)d_in[3];
    const float* w2 = (const float*)d_in[4];
    const float* b2 = (const float*)d_in[5];
    const float* wc = (const float*)d_in[6];
    const float* bc = (const float*)d_in[7];

    float* out = (float*)d_out;
    float* out_logits = out;                 // [B]
    float* out_pooled = out + B_;            // [B, D]
    float* out_attn   = out + B_ + B_ * D_;  // [B, N]

    cudaFuncSetAttribute(gemm1_kernel,
                         cudaFuncAttributeMaxDynamicSharedMemorySize, SMEM_BYTES);

    prep_kernel<<<(H_ * D_) / 256, 256>>>(w1);
    gemm1_kernel<<<(B_ * N_) / 128, 256, SMEM_BYTES>>>(feats, b1, w2, b2, mask);
    tail_kernel<<<(B_ * N_) / 256 + (B_ * D_) / 256, 256>>>(out_attn, out_pooled);
    final_kernel<<<B_, 256>>>(out_pooled, wc, bc, out_logits);
}

// round 15
// speedup vs baseline: 2.2126x; 1.0006x over previous
#include <cuda_runtime.h>
#include <cuda_fp16.h>
#include <mma.h>
#include <cstdint>
#include <math.h>

using namespace nvcuda;

#define B_ 32
#define N_ 8192
#define D_ 1024
#define H_ 128
#define CPB 64          // CTAs per batch in gemm1 (8192/128)

// ---------------- scratch (no cudaMalloc allowed) ----------------
__device__ __align__(16) unsigned short g_w1t[H_ * D_];   // fp16 W1^T [h][d]
__device__ __align__(16) float g_e[B_ * N_];              // mask*exp(logit)
__device__ __align__(16) float g_erow[B_ * CPB];          // per-CTA e sums
__device__ __align__(16) float g_part[B_ * CPB * D_];     // unscaled pooled partials (8 MB)

// ---------------- helpers ----------------
__device__ __forceinline__ uint32_t smem_u32(const void* p) {
    uint32_t a;
    asm("{ .reg .u64 t; cvta.to.shared.u64 t, %1; cvt.u32.u64 %0, t; }" : "=r"(a) : "l"(p));
    return a;
}
__device__ __forceinline__ void cpasync16(uint32_t dst, const void* src) {
    asm volatile("cp.async.cg.shared.global [%0], [%1], 16;"
                 :: "r"(dst), "l"(src) : "memory");
}

// ---------------- kernel 0: W1^T -> fp16 ----------------
__global__ void prep_kernel(const float* __restrict__ w1) {
    int idx = blockIdx.x * 256 + threadIdx.x;   // 0..H*D-1
    int h = idx >> 10, d = idx & 1023;
    g_w1t[idx] = __half_as_ushort(__float2half_rn(w1[(size_t)d * H_ + h]));
}

// ---------------- kernel 1: GEMM1 + tanh + fc2 + exp*mask + weighted pool ----------------
static constexpr int ROWE = 72;                  // row stride in fp16 elements
static constexpr int ROWB = 144;                 // row stride bytes (128 data + 16 pad)
static constexpr int TILE = 128 * ROWB;          // 18432 bytes per 128x64 tile
static constexpr int OFF_B1   = 0;               // 512 B
static constexpr int OFF_W2   = 512;             // 512 B
static constexpr int OFF_PART = 1024;            // 1024 B
static constexpr int OFF_SCR  = 2048;            // 8 warps * 256 floats = 8192 B
static constexpr int OFF_A0   = 10240;           // A fp16 ping-pong
static constexpr int OFF_A1   = OFF_A0 + TILE;
static constexpr int OFF_BB0  = OFF_A1 + TILE;   // B fp16 ping-pong
static constexpr int OFF_BB1  = OFF_BB0 + TILE;
static constexpr int SMEM_BYTES = OFF_BB1 + TILE;   // 83968

__global__ void __launch_bounds__(256, 2)
gemm1_kernel(const float* __restrict__ feats, const float* __restrict__ b1,
             const float* __restrict__ w2, const float* __restrict__ b2,
             const int* __restrict__ mask) {
    extern __shared__ char dsm[];
    uint32_t sb = smem_u32(dsm);
    float* b1s  = (float*)(dsm + OFF_B1);
    float* w2s  = (float*)(dsm + OFF_W2);
    float* part = (float*)(dsm + OFF_PART);
    float* scr  = (float*)(dsm + OFF_SCR);
    float* sa   = scr;                            // e values [128] (post-epilogue reuse)

    int tid = threadIdx.x;
    int lane = tid & 31, warp = tid >> 5;
    int warp_m = warp >> 1, warp_n = warp & 1;   // 4 x 2 warp grid
    int m_base = warp_m * 32, n_base = warp_n * 64;

    if (tid < 128) { b1s[tid] = b1[tid]; w2s[tid] = w2[tid]; }

    const float* A0 = feats + (size_t)blockIdx.x * 128 * D_;

    // staging indices
    int ar = tid >> 4, ac4 = tid & 15;   // A: 8 iters x (row, float4-col)
    int bn = tid >> 3, bcu = tid & 7;    // B: 4 iters x (row, 16B-col)

    wmma::fragment<wmma::accumulator, 16, 16, 16, float> cfr[2][4];
    #pragma unroll
    for (int mi = 0; mi < 2; mi++)
        #pragma unroll
        for (int ni = 0; ni < 4; ni++)
            wmma::fill_fragment(cfr[mi][ni], 0.0f);

    auto ldg_a = [&](float4* av, int kc) {
        #pragma unroll
        for (int i = 0; i < 8; i++) {
            int r = ar + i * 16;
            av[i] = __ldg((const float4*)(A0 + (size_t)r * D_ + kc * 64) + ac4);
        }
    };
    auto sts_a = [&](const float4* av, int buf) {
        uint32_t base = sb + (buf ? OFF_A1 : OFF_A0);
        #pragma unroll
        for (int i = 0; i < 8; i++) {
            int r = ar + i * 16;
            uint32_t off = (uint32_t)(r * ROWB + ac4 * 8);
            __half2 h01 = __floats2half2_rn(av[i].x, av[i].y);
            __half2 h23 = __floats2half2_rn(av[i].z, av[i].w);
            asm volatile("st.shared.v2.b32 [%0], {%1, %2};"
                         :: "r"(base + off),
                            "r"(*(uint32_t*)&h01), "r"(*(uint32_t*)&h23) : "memory");
        }
    };
    auto cpa_b = [&](int kc, int buf) {
        uint32_t dbb = sb + (buf ? OFF_BB1 : OFF_BB0);
        #pragma unroll
        for (int i = 0; i < 4; i++) {
            int n = bn + i * 32;
            cpasync16(dbb + (uint32_t)(n * ROWB + bcu * 16),
                      g_w1t + (size_t)n * D_ + kc * 64 + bcu * 8);
        }
        asm volatile("cp.async.commit_group;" ::: "memory");
    };
    auto compute = [&](int buf) {
        const __half* As = (const __half*)(dsm + (buf ? OFF_A1 : OFF_A0));
        const __half* Bs = (const __half*)(dsm + (buf ? OFF_BB1 : OFF_BB0));
        #pragma unroll
        for (int ks = 0; ks < 4; ks++) {
            wmma::fragment<wmma::matrix_a, 16, 16, 16, __half, wmma::row_major> af[2];
            #pragma unroll
            for (int mi = 0; mi < 2; mi++) {
                const __half* pa = As + (size_t)(m_base + mi * 16) * ROWE + ks * 16;
                wmma::load_matrix_sync(af[mi], pa, ROWE);
            }
            #pragma unroll
            for (int ni = 0; ni < 4; ni++) {
                wmma::fragment<wmma::matrix_b, 16, 16, 16, __half, wmma::col_major> bf;
                const __half* pb = Bs + (size_t)(n_base + ni * 16) * ROWE + ks * 16;
                wmma::load_matrix_sync(bf, pb, ROWE);
                #pragma unroll
                for (int mi = 0; mi < 2; mi++)
                    wmma::mma_sync(cfr[mi][ni], af[mi], bf, cfr[mi][ni]);
            }
        }
    };

    // ---- prologue: stage chunk 0 into buffer 0 ----
    {
        float4 av[8];
        cpa_b(0, 0);
        ldg_a(av, 0);
        sts_a(av, 0);
        asm volatile("cp.async.wait_group 0;" ::: "memory");
    }
    __syncthreads();

    // ---- main loop: A and B double-buffered, ONE sync per chunk ----
    #pragma unroll 1
    for (int kc = 0; kc < 16; kc++) {
        int buf = kc & 1;
        float4 av[8];
        if (kc < 15) {
            ldg_a(av, kc + 1);
            cpa_b(kc + 1, buf ^ 1);
        }
        compute(buf);
        if (kc < 15) {
            sts_a(av, buf ^ 1);
            asm volatile("cp.async.wait_group 0;" ::: "memory");
        }
        __syncthreads();
    }

    // ---- epilogue part 1: p(row) = sum_j w2_j * tanh(c + b1_j) ----
    {
        float* ws = scr + warp * 256;
        int r16 = lane & 15, ch = (lane >> 4) * 8;
        float pacc[2] = {0.0f, 0.0f};
        #pragma unroll
        for (int mi = 0; mi < 2; mi++) {
            #pragma unroll
            for (int ni = 0; ni < 4; ni++) {
                wmma::store_matrix_sync(ws, cfr[mi][ni], 16, wmma::mem_row_major);
                __syncwarp();
                float s = 0.0f;
                #pragma unroll
                for (int j = 0; j < 8; j++) {
                    int col = n_base + ni * 16 + ch + j;
                    float v = ws[r16 * 16 + ch + j];
                    s += w2s[col] * tanhf(v + b1s[col]);
                }
                pacc[mi] += s;
                __syncwarp();
            }
        }
        #pragma unroll
        for (int mi = 0; mi < 2; mi++) {
            float tot = pacc[mi] + __shfl_xor_sync(0xffffffffu, pacc[mi], 16);
            if (lane < 16) {
                int row = m_base + mi * 16 + r16;
                part[row * 2 + warp_n] = tot;
            }
        }
    }
    __syncthreads();

    // ---- epilogue part 2: e = mask * exp(logit) ----
    int batch = blockIdx.x >> 6;
    int nidx = ((blockIdx.x & 63) << 7) + tid;
    if (tid < 128) {
        float logit = part[tid * 2] + part[tid * 2 + 1] + b2[0];
        int m = mask[(size_t)batch * N_ + nidx];
        float e = m ? expf(logit) : 0.0f;
        g_e[(size_t)batch * N_ + nidx] = e;
        sa[tid] = e;                 // scr region, safe after part-1 done
    }
    __syncthreads();

    // ---- epilogue part 3: unscaled weighted pool; tile is L2-hot ----
    {
        float4 acc = make_float4(0.f, 0.f, 0.f, 0.f);
        const float4* fp = (const float4*)A0 + tid;   // thread t owns float4-col t
        #pragma unroll 8
        for (int n = 0; n < 128; n++) {
            float a = sa[n];
            float4 v = __ldg(fp + (size_t)n * 256);
            acc.x += a * v.x; acc.y += a * v.y; acc.z += a * v.z; acc.w += a * v.w;
        }
        ((float4*)(g_part + (size_t)blockIdx.x * D_))[tid] = acc;
    }
    __syncthreads();

    // ---- epilogue part 4: per-CTA e sum (tree over sa) ----
    #pragma unroll
    for (int o = 64; o > 0; o >>= 1) {
        if (tid < o) sa[tid] += sa[tid + o];
        __syncthreads();
    }
    if (tid == 0) g_erow[blockIdx.x] = sa[0];
}

// ---------------- kernel 2: fused tail ----------------
// blocks [0,1024): attn = e/S ; [1024,1152): pooled ; [1152,1184): logits
__global__ void tail_kernel(float* __restrict__ attn, float* __restrict__ pooled,
                            const float* __restrict__ wc, const float* __restrict__ bc,
                            float* __restrict__ logits) {
    __shared__ float red[64];
    __shared__ float red2[256];
    int bid = blockIdx.x;
    int t = threadIdx.x;
    if (bid < 1024) {
        // attn over B*N
        int idx = bid * 256 + t;
        int b = idx >> 13;
        if (t < 64) red[t] = g_erow[b * CPB + t];
        __syncthreads();
        #pragma unroll
        for (int o = 32; o > 0; o >>= 1) {
            if (t < o) red[t] += red[t + o];
            __syncthreads();
        }
        float inv = 1.0f / fmaxf(red[0], 1e-8f);
        attn[idx] = g_e[idx] * inv;
    } else if (bid < 1152) {
        // pooled over B*D
        int idx = (bid - 1024) * 256 + t;
        int b = idx >> 10, d = idx & 1023;
        if (t < 64) red[t] = g_erow[b * CPB + t];
        __syncthreads();
        #pragma unroll
        for (int o = 32; o > 0; o >>= 1) {
            if (t < o) red[t] += red[t + o];
            __syncthreads();
        }
        float inv = 1.0f / fmaxf(red[0], 1e-8f);
        float acc = 0.0f;
        #pragma unroll
        for (int s = 0; s < CPB; s++)
            acc += g_part[((size_t)b * CPB + s) * D_ + d];
        pooled[idx] = acc * inv;
    } else {
        // logits per batch: recompute pooled from g_part (no dependency on pooled)
        int b = bid - 1152;
        if (t < 64) red[t] = g_erow[b * CPB + t];
        __syncthreads();
        #pragma unroll
        for (int o = 32; o > 0; o >>= 1) {
            if (t < o) red[t] += red[t + o];
            __syncthreads();
        }
        float inv = 1.0f / fmaxf(red[0], 1e-8f);
        float acc = 0.0f;
        #pragma unroll
        for (int j = 0; j < 4; j++) {
            int d = t + j * 256;
            float ps = 0.0f;
            #pragma unroll
            for (int s = 0; s < CPB; s++)
                ps += g_part[((size_t)b * CPB + s) * D_ + d];
            acc += ps * inv * wc[d];
        }
        red2[t] = acc;
        __syncthreads();
        #pragma unroll
        for (int o = 128; o > 0; o >>= 1) {
            if (t < o) red2[t] += red2[t + o];
            __syncthreads();
        }
        if (t == 0) logits[b] = red2[0] + bc[0];
    }
}

// ---------------- launch ----------------
extern "C" void kernel_launch(void* const* d_in, const int* in_sizes, int n_in,
                              void* d_out, int out_size) {
    const float* feats = (const float*)d_in[0];
    const int* mask = (const int*)d_in[1];       // jnp.bool_ -> int32
    const float* w1 = (const float*)d_in[2];
    const float* b1 = (const float*)d_in[3];
    const float* w2 = (const float*)d_in[4];
    const float* b2 = (const float*)d_in[5];
    const float* wc = (const float*)d_in[6];
    const float* bc = (const float*)d_in[7];

    float* out = (float*)d_out;
    float* out_logits = out;                 // [B]
    float* out_pooled = out + B_;            // [B, D]
    float* out_attn   = out + B_ + B_ * D_;  // [B, N]

    cudaFuncSetAttribute(gemm1_kernel,
                         cudaFuncAttributeMaxDynamicSharedMemorySize, SMEM_BYTES);

    prep_kernel<<<(H_ * D_) / 256, 256>>>(w1);
    gemm1_kernel<<<(B_ * N_) / 128, 256, SMEM_BYTES>>>(feats, b1, w2, b2, mask);
    tail_kernel<<<(B_ * N_) / 256 + (B_ * D_) / 256 + B_, 256>>>(
        out_attn, out_pooled, wc, bc, out_logits);
}